// round 1
// baseline (speedup 1.0000x reference)
#include <cuda_runtime.h>
#include <math.h>

#define NPTS (32*64*64)   // 131072 points
#define D 64
#define KC 512
#define ROWPAD 68         // padded smem row stride (floats) to dodge bank conflicts on transpose store

// ---------------- scratch (device globals; no allocations allowed) ----------------
__device__ int   g_idx[NPTS];
__device__ float g_counts[KC];
__device__ float g_embedsum[KC*D];   // [k][d] layout
__device__ float g_losssum;

// ---------------- K0: zero scratch (must run every graph replay) ----------------
__global__ void k0_zero() {
    int i = blockIdx.x*blockDim.x + threadIdx.x;
    if (i < KC)    g_counts[i] = 0.f;
    if (i < KC*D)  g_embedsum[i] = 0.f;
    if (i == 0)    g_losssum = 0.f;
}

// ---------------- K1: distances + argmin + quantized + histogram + loss ----------------
// grid: NPTS/256 blocks, 256 threads, 1 point/thread. E resident in smem [k][d] padded.
__global__ void __launch_bounds__(256) k1_argmin(
    const float* __restrict__ z, const float* __restrict__ E, float* __restrict__ outq)
{
    extern __shared__ float sE[];        // KC*ROWPAD floats (139264 B)
    __shared__ float sEk2[KC];
    __shared__ int   sHist[KC];
    __shared__ float sWarp[8];
    const int tid = threadIdx.x;

    // load + transpose E: gmem [d][k] -> smem [k][d] (padded)
    for (int i = tid; i < D*KC; i += 256) {
        int d = i >> 9, k = i & (KC-1);
        sE[k*ROWPAD + d] = E[i];
    }
    for (int i = tid; i < KC; i += 256) sHist[i] = 0;
    __syncthreads();

    // per-code squared norms
    for (int k = tid; k < KC; k += 256) {
        const float* row = sE + k*ROWPAD;
        float s = 0.f;
        #pragma unroll 16
        for (int d = 0; d < D; d++) s = fmaf(row[d], row[d], s);
        sEk2[k] = s;
    }
    __syncthreads();

    const int point = blockIdx.x*256 + tid;

    float4 zr[16];
    {
        const float4* zp = (const float4*)(z + (size_t)point*D);
        #pragma unroll
        for (int j = 0; j < 16; j++) zr[j] = zp[j];
    }

    float best1 = 3.4e38f, best2 = 3.4e38f;
    int k1 = 0, k2 = 0;
    for (int k = 0; k < KC; k++) {
        const float4* e4 = (const float4*)(sE + k*ROWPAD);
        float a0 = 0.f, a1 = 0.f, a2 = 0.f, a3 = 0.f;
        #pragma unroll
        for (int j = 0; j < 16; j++) {
            float4 e = e4[j];
            a0 = fmaf(zr[j].x, e.x, a0);
            a1 = fmaf(zr[j].y, e.y, a1);
            a2 = fmaf(zr[j].z, e.z, a2);
            a3 = fmaf(zr[j].w, e.w, a3);
        }
        float score = fmaf(-2.f, (a0+a1)+(a2+a3), sEk2[k]);  // ||e||^2 - 2 z.e
        if (score < best1)      { best2 = best1; k2 = k1; best1 = score; k1 = k; }
        else if (score < best2) { best2 = score; k2 = k; }
    }

    // near-tie: refine top-2 in fp64 (exact squared distance), first-occurrence tiebreak
    if (best2 - best1 < 1e-3f) {
        const float* r1 = sE + k1*ROWPAD;
        const float* r2 = sE + k2*ROWPAD;
        double dd1 = 0.0, dd2 = 0.0;
        #pragma unroll
        for (int j = 0; j < 16; j++) {
            double zx = zr[j].x, zy = zr[j].y, zz = zr[j].z, zw = zr[j].w;
            double t;
            t = zx - (double)r1[4*j+0]; dd1 += t*t;
            t = zy - (double)r1[4*j+1]; dd1 += t*t;
            t = zz - (double)r1[4*j+2]; dd1 += t*t;
            t = zw - (double)r1[4*j+3]; dd1 += t*t;
            t = zx - (double)r2[4*j+0]; dd2 += t*t;
            t = zy - (double)r2[4*j+1]; dd2 += t*t;
            t = zz - (double)r2[4*j+2]; dd2 += t*t;
            t = zw - (double)r2[4*j+3]; dd2 += t*t;
        }
        if (dd2 < dd1 || (dd2 == dd1 && k2 < k1)) { int tk = k1; k1 = k2; k2 = tk; }
    }

    const int id = k1;
    g_idx[point] = id;
    atomicAdd(&sHist[id], 1);

    // loss contribution: sum_d (e_d - z_d)^2
    float ls = 0.f;
    {
        const float* er = sE + id*ROWPAD;
        #pragma unroll
        for (int j = 0; j < 16; j++) {
            float dx = er[4*j+0] - zr[j].x; ls = fmaf(dx, dx, ls);
            float dy = er[4*j+1] - zr[j].y; ls = fmaf(dy, dy, ls);
            float dz = er[4*j+2] - zr[j].z; ls = fmaf(dz, dz, ls);
            float dw = er[4*j+3] - zr[j].w; ls = fmaf(dw, dw, ls);
        }
    }
    #pragma unroll
    for (int o = 16; o; o >>= 1) ls += __shfl_down_sync(0xffffffffu, ls, o);
    if ((tid & 31) == 0) sWarp[tid >> 5] = ls;
    __syncthreads();
    if (tid < 8) {
        float v = sWarp[tid];
        #pragma unroll
        for (int o = 4; o; o >>= 1) v += __shfl_down_sync(0xffu, v, o);
        if (tid == 0) atomicAdd(&g_losssum, v);
    }

    // warp-cooperative coalesced quantized store: quantized[n][d] = E[d][idx_n]
    {
        const int lane = tid & 31;
        const int wbase = point - lane;
        for (int p = 0; p < 32; p++) {
            int idp = __shfl_sync(0xffffffffu, id, p);
            const float2* row = (const float2*)(sE + idp*ROWPAD);
            float2 q = row[lane];  // d = 2*lane, 2*lane+1
            ((float2*)(outq + (size_t)(wbase + p)*D))[lane] = q;
        }
    }

    // flush histogram
    __syncthreads();
    for (int i = tid; i < KC; i += 256) {
        int c = sHist[i];
        if (c) atomicAdd(&g_counts[i], (float)c);
    }
}

// ---------------- K2: embed_sum[k][d] += z over points with idx==k ----------------
// grid: 148 blocks x 256 threads; smem accumulation then gmem atomic flush.
__global__ void __launch_bounds__(256) k2_embedsum(const float* __restrict__ z)
{
    extern __shared__ float sSum[];   // KC*D floats (131072 B)
    const int tid = threadIdx.x;
    for (int i = tid; i < KC*D; i += 256) sSum[i] = 0.f;
    __syncthreads();

    const int per = (NPTS + gridDim.x - 1) / gridDim.x;
    const int p0 = blockIdx.x * per;
    const int p1 = min(p0 + per, NPTS);
    const int pl = tid >> 6;       // 4 points handled per iteration
    const int d  = tid & 63;

    for (int p = p0 + pl; p < p1; p += 4) {
        int id = g_idx[p];
        float v = z[(size_t)p*D + d];
        atomicAdd(&sSum[id*D + d], v);
    }
    __syncthreads();

    for (int i = tid; i < KC*D; i += 256) {
        float v = sSum[i];
        if (v != 0.f) atomicAdd(&g_embedsum[i], v);
    }
}

// ---------------- K3: EMA updates, smoothing, final outputs ----------------
__global__ void __launch_bounds__(512) k3_finalize(
    const float* __restrict__ cs, const float* __restrict__ ea, float* __restrict__ out)
{
    float* out_loss = out + (size_t)NPTS * D;   // 8388608
    float* out_emb  = out_loss + 1;             // new_embedding [D,K]
    float* out_ncs  = out_emb + KC*D;           // new_cluster_size [K]
    float* out_nea  = out_ncs + KC;             // new_embed_avg [D,K]

    __shared__ float sRed[16];
    __shared__ float sN;
    const int t = threadIdx.x;

    float ncs = cs[t]*0.99f + 0.01f*g_counts[t];
    out_ncs[t] = ncs;

    // block reduce: n = sum(new_cluster_size)
    float v = ncs;
    #pragma unroll
    for (int o = 16; o; o >>= 1) v += __shfl_down_sync(0xffffffffu, v, o);
    if ((t & 31) == 0) sRed[t >> 5] = v;
    __syncthreads();
    if (t < 16) {
        float w = sRed[t];
        #pragma unroll
        for (int o = 8; o; o >>= 1) w += __shfl_down_sync(0xffffu, w, o);
        if (t == 0) sN = w;
    }
    __syncthreads();
    const float n = sN;
    const float sm = (ncs + 1e-5f) / (n + (float)KC * 1e-5f) * n;

    for (int dd = 0; dd < D; dd++) {
        int i = dd*KC + t;                              // [D,K] row-major
        float nea = ea[i]*0.99f + 0.01f*g_embedsum[t*D + dd];
        out_nea[i] = nea;
        out_emb[i] = nea / sm;
    }
    if (t == 0) out_loss[0] = 0.25f * (g_losssum / (float)((size_t)NPTS * D));
}

// ---------------- launch ----------------
extern "C" void kernel_launch(void* const* d_in, const int* in_sizes, int n_in,
                              void* d_out, int out_size)
{
    const float* z  = (const float*)d_in[0];   // [32,64,64,64]
    const float* E  = (const float*)d_in[1];   // [64,512]
    const float* cs = (const float*)d_in[2];   // [512]
    const float* ea = (const float*)d_in[3];   // [64,512]
    float* out = (float*)d_out;

    cudaFuncSetAttribute(k1_argmin,   cudaFuncAttributeMaxDynamicSharedMemorySize, KC*ROWPAD*4);
    cudaFuncSetAttribute(k2_embedsum, cudaFuncAttributeMaxDynamicSharedMemorySize, KC*D*4);

    k0_zero<<<(KC*D + 255)/256, 256>>>();
    k1_argmin<<<NPTS/256, 256, KC*ROWPAD*4>>>(z, E, out);
    k2_embedsum<<<148, 256, KC*D*4>>>(z);
    k3_finalize<<<1, 512>>>(cs, ea, out);
}